// round 11
// baseline (speedup 1.0000x reference)
#include <cuda_runtime.h>
#include <cuda_bf16.h>
#include <cstdint>

// VectorQuantizer forward (GB300, mma.sync bf16 HMMA):
//   out  = x  (reference returns the rearranged input == x bit-exactly)
//   loss = 1.25/(N*E) * ( sum(x^2) + sum_n min_k( ||e_k||^2 - 2 x_n . e_k ) )
// N=32768, E=256, K=1024.  x: [32,256,32,32] (vector n=(b,hw), dim stride 1024).
// out-copy + sum(x^2) fused into the GEMM's A-build; loss finalize fused into
// the last-finishing CTA.

#define NVEC  32768
#define EDIM  256
#define KCODE 1024

#define CTA_M 128
#define CTA_N 128             // codes per chunk
#define NCH   (KCODE/CTA_N)   // 8
#define KT    64              // dims per B tile
#define NT    (NCH*(EDIM/KT)) // 32 B tiles total

// smem layout (bytes).  A: 128 rows x 512B, XOR-swizzled (no pad).
#define SM_A   0              // 65536
#define SM_B0  65536          // 16384 (128 codes x 128B, swizzled)
#define SM_B1  81920          // 16384
#define SM_XS  98304          // 2 x 8192 f32 stage [16 c][128 hw] (phase 1)
#define SM_EN  98304          // 4096  (reuses XS after phase 1)
#define SM_RM  102400         // 2048
#define SMEM_TOTAL 114688     // x2 CTAs = 229376 <= 228KB/SM

__device__ double g_sumx2;
__device__ double g_summin;
__device__ unsigned g_count;
__device__ float  g_enorm2[KCODE];
__device__ __nv_bfloat16 g_cbb[(size_t)KCODE * EDIM];

// ---------------- PTX helpers ----------------
__device__ __forceinline__ uint32_t smem_u32(const void* p) {
    uint32_t a;
    asm("{ .reg .u64 t; cvta.to.shared.u64 t, %1; cvt.u32.u64 %0, t; }"
        : "=r"(a) : "l"(p));
    return a;
}
__device__ __forceinline__ uint32_t pack_bf16x2(float lo, float hi) {
    uint32_t r;
    asm("cvt.rn.bf16x2.f32 %0, %1, %2;" : "=r"(r) : "f"(hi), "f"(lo));
    return r;
}
__device__ __forceinline__ void ldsm_x4(uint32_t* r, uint32_t addr) {
    asm volatile("ldmatrix.sync.aligned.m8n8.x4.shared.b16 {%0,%1,%2,%3}, [%4];"
                 : "=r"(r[0]), "=r"(r[1]), "=r"(r[2]), "=r"(r[3]) : "r"(addr));
}
__device__ __forceinline__ void ldsm_x4t(uint32_t* r, uint32_t addr) {
    asm volatile("ldmatrix.sync.aligned.m8n8.x4.trans.shared.b16 {%0,%1,%2,%3}, [%4];"
                 : "=r"(r[0]), "=r"(r[1]), "=r"(r[2]), "=r"(r[3]) : "r"(addr));
}
__device__ __forceinline__ void mma16816(float* d, const uint32_t* a, const uint32_t* b) {
    asm volatile(
        "mma.sync.aligned.m16n8k16.row.col.f32.bf16.bf16.f32 "
        "{%0,%1,%2,%3}, {%4,%5,%6,%7}, {%8,%9}, {%0,%1,%2,%3};"
        : "+f"(d[0]), "+f"(d[1]), "+f"(d[2]), "+f"(d[3])
        : "r"(a[0]), "r"(a[1]), "r"(a[2]), "r"(a[3]), "r"(b[0]), "r"(b[1]));
}
#define CP_ASYNC16(s, g) \
    asm volatile("cp.async.cg.shared.global [%0], [%1], 16;" :: "r"(s), "l"(g))
#define CP_COMMIT() asm volatile("cp.async.commit_group;" ::: "memory")
#define CP_WAIT1()  asm volatile("cp.async.wait_group 1;" ::: "memory")
#define CP_WAIT0()  asm volatile("cp.async.wait_group 0;" ::: "memory")

// ---------------- prep: init + codebook bf16 + ||e||^2 ----------------
__global__ void prep_kernel(const float* __restrict__ cb) {
    int tid = threadIdx.x;                           // 256 blocks x 256 threads
    int j = blockIdx.x * 256 + tid;                  // float4 index, 0..65535
    if (j == 0) { g_sumx2 = 0.0; g_summin = 0.0; g_count = 0u; }
    float4 v = ((const float4*)cb)[j];
    uint2 p;
    p.x = pack_bf16x2(v.x, v.y);
    p.y = pack_bf16x2(v.z, v.w);
    ((uint2*)g_cbb)[j] = p;
    float s = v.x * v.x + v.y * v.y + v.z * v.z + v.w * v.w;
#pragma unroll
    for (int o = 16; o; o >>= 1) s += __shfl_xor_sync(0xffffffffu, s, o);
    __shared__ float aa[8];
    if ((tid & 31) == 0) aa[tid >> 5] = s;
    __syncthreads();
    if ((tid & 63) == 0) {
        int g = tid >> 6;                            // code within block (4/block)
        g_enorm2[blockIdx.x * 4 + g] = aa[2 * g] + aa[2 * g + 1];
    }
}

// ---------------- fused GEMM + row-min + sum(x^2) + out-copy + loss ----------------
extern __shared__ __align__(1024) unsigned char smem[];

// B tile t: chunk nc=t>>2, k-slice kt=t&3.  128 codes x 64 dims bf16 = 128B/row,
// XOR-swizzled ((row&7)<<4).
__device__ __forceinline__ void issueB(uint32_t sb, int tid, int t) {
    uint32_t dstb = sb + ((t & 1) ? SM_B1 : SM_B0);
    const char* gp = (const char*)g_cbb + (size_t)(t >> 2) * (128 * 512)
                   + (size_t)(t & 3) * 128;
#pragma unroll
    for (int s = 0; s < 4; ++s) {
        int i = tid + s * 256;
        int r = i >> 3;
        uint32_t c = (uint32_t)(i & 7) * 16;
        CP_ASYNC16(dstb + (uint32_t)r * 128 + (c ^ ((uint32_t)(r & 7) << 4)),
                   gp + (size_t)r * 512 + c);
    }
}

// X stage q: dims [q*16, q*16+16), 128 rows of f32 -> xs buffer (q&1)
__device__ __forceinline__ void issueX(uint32_t sb, const float* xb, int tid, int q) {
    uint32_t dst = sb + SM_XS + (uint32_t)(q & 1) * 8192;
    const char* gp = (const char*)xb + (size_t)q * 16 * 4096;
#pragma unroll
    for (int s = 0; s < 2; ++s) {
        int j = tid + s * 256;                       // 0..511 (16B chunks)
        int c = j >> 5;
        uint32_t off = (uint32_t)(j & 31) * 16;
        CP_ASYNC16(dst + (uint32_t)c * 512 + off, gp + (size_t)c * 4096 + off);
    }
}

__global__ __launch_bounds__(256, 2) void vq_mma_kernel(const float* __restrict__ x,
                                                        float* __restrict__ out,
                                                        long long loss_idx) {
    uint32_t sb = smem_u32(smem);
    int tid = threadIdx.x, lane = tid & 31, wid = tid >> 5;
    int wm = wid >> 2, wn = wid & 3;

    // ---- Phase 1: cp.async-pipelined A build + out copy + sum(x^2) ----
    int n0 = blockIdx.x * CTA_M;
    int b = n0 >> 10, hw0 = n0 & 1023;
    const float* xb = x + (size_t)b * (EDIM * 1024) + hw0;
    float* ob = out + (size_t)b * (EDIM * 1024) + hw0;
    float* xs = (float*)(smem + SM_XS);
    int row = tid & 127, h = tid >> 7;
    uint32_t sxp = (uint32_t)(row & 7) << 4;
    float sq = 0.f;

    issueX(sb, xb, tid, 0); CP_COMMIT();
    issueX(sb, xb, tid, 1); CP_COMMIT();
#pragma unroll 1
    for (int q = 0; q < 16; ++q) {
        // stage q is the NEWEST committed group at q==15 -> must drain fully there
        if (q < 15) CP_WAIT1(); else CP_WAIT0();
        __syncthreads();
        float* buf = xs + (q & 1) * 2048;
        // out-copy + sum(x^2), coalesced in x layout
#pragma unroll
        for (int s = 0; s < 2; ++s) {
            int j = tid + s * 256;                   // 0..511 float4 slots
            int c = j >> 5, m = (j & 31) * 4;
            float4 v = *(float4*)(buf + c * 128 + m);
            *(float4*)(ob + (size_t)(q * 16 + c) * 1024 + m) = v;
            sq += v.x * v.x + v.y * v.y + v.z * v.z + v.w * v.w;
        }
        // transpose-pack to bf16 A
        float v[8];
#pragma unroll
        for (int m = 0; m < 8; ++m) v[m] = buf[(h * 8 + m) * 128 + row];
        uint4 w;
        w.x = pack_bf16x2(v[0], v[1]); w.y = pack_bf16x2(v[2], v[3]);
        w.z = pack_bf16x2(v[4], v[5]); w.w = pack_bf16x2(v[6], v[7]);
        uint32_t col = (uint32_t)(q * 32 + h * 16);
        *(uint4*)(smem + SM_A + row * 512 + (col ^ sxp)) = w;
        __syncthreads();
        if (q + 2 < 16) { issueX(sb, xb, tid, q + 2); CP_COMMIT(); }
    }
    // B tiles 0,1 (xs region now dead; EN overlays it)
    issueB(sb, tid, 0); CP_COMMIT();
    issueB(sb, tid, 1); CP_COMMIT();
    {
        float4 e4 = ((const float4*)g_enorm2)[tid];
        *(float4*)(smem + SM_EN + tid * 16) = e4;
    }

    // ---- mainloop ----
    uint32_t sxl = (uint32_t)(lane & 7) << 4;
    uint32_t abase[4];
#pragma unroll
    for (int mi = 0; mi < 4; ++mi)
        abase[mi] = sb + SM_A + (uint32_t)(wm * 64 + mi * 16 + (lane & 15)) * 512;
    uint32_t colA_l = (uint32_t)(lane >> 4) * 16;
    uint32_t brow0  = (uint32_t)(wn * 32 + (lane & 7) + ((lane >> 4) & 1) * 8) * 128;
    uint32_t colB_l = (uint32_t)((lane >> 3) & 1) * 16;

    float regmin[8];
#pragma unroll
    for (int i = 0; i < 8; ++i) regmin[i] = 3.0e38f;

#pragma unroll 1
    for (int nc = 0; nc < NCH; ++nc) {
        float acc[4][4][4];
#pragma unroll
        for (int mi = 0; mi < 4; ++mi)
#pragma unroll
            for (int nj = 0; nj < 4; ++nj)
#pragma unroll
                for (int c = 0; c < 4; ++c) acc[mi][nj][c] = 0.f;

#pragma unroll 1
        for (int kt = 0; kt < 4; ++kt) {
            int t = nc * 4 + kt;
            if (t < NT - 2) CP_WAIT1(); else CP_WAIT0();
            __syncthreads();
            uint32_t bufb = sb + ((t & 1) ? SM_B1 : SM_B0);
#pragma unroll
            for (int kq = 0; kq < 4; ++kq) {
                uint32_t cA = (uint32_t)(kt * 128 + kq * 32) + colA_l;
                uint32_t cB = (uint32_t)(kq * 32) + colB_l;
                uint32_t bf[2][4];
                ldsm_x4t(bf[0], bufb + brow0 + (cB ^ sxl));
                ldsm_x4t(bf[1], bufb + brow0 + 16 * 128 + (cB ^ sxl));
#pragma unroll
                for (int mi = 0; mi < 4; ++mi) {
                    uint32_t af[4];
                    ldsm_x4(af, abase[mi] + (cA ^ sxl));
                    mma16816(acc[mi][0], af, &bf[0][0]);
                    mma16816(acc[mi][1], af, &bf[0][2]);
                    mma16816(acc[mi][2], af, &bf[1][0]);
                    mma16816(acc[mi][3], af, &bf[1][2]);
                }
            }
            __syncthreads();
            if (t + 2 < NT) { issueB(sb, tid, t + 2); CP_COMMIT(); }
        }
        // epilogue: fold en[k] - 2*dot into per-lane row minima
        const float* en = (const float*)(smem + SM_EN) + nc * 128;
#pragma unroll
        for (int nj = 0; nj < 4; ++nj) {
            int col = wn * 32 + nj * 8 + (lane & 3) * 2;
            float e0 = en[col], e1 = en[col + 1];
#pragma unroll
            for (int mi = 0; mi < 4; ++mi) {
                float s0 = fmaf(acc[mi][nj][0], -2.f, e0);
                float s1 = fmaf(acc[mi][nj][1], -2.f, e1);
                float s2 = fmaf(acc[mi][nj][2], -2.f, e0);
                float s3 = fmaf(acc[mi][nj][3], -2.f, e1);
                regmin[mi * 2 + 0] = fminf(regmin[mi * 2 + 0], fminf(s0, s1));
                regmin[mi * 2 + 1] = fminf(regmin[mi * 2 + 1], fminf(s2, s3));
            }
        }
    }

    // ---- reductions ----
#pragma unroll
    for (int i = 0; i < 8; ++i) {
        regmin[i] = fminf(regmin[i], __shfl_xor_sync(0xffffffffu, regmin[i], 1));
        regmin[i] = fminf(regmin[i], __shfl_xor_sync(0xffffffffu, regmin[i], 2));
    }
    float* rm = (float*)(smem + SM_RM);              // rm[wn][128]
    __syncthreads();
    if ((lane & 3) == 0) {
        int g = lane >> 2;
#pragma unroll
        for (int mi = 0; mi < 4; ++mi) {
            int r = wm * 64 + mi * 16 + g;
            rm[wn * 128 + r]     = regmin[mi * 2 + 0];
            rm[wn * 128 + r + 8] = regmin[mi * 2 + 1];
        }
    }
    __syncthreads();

    __shared__ float ws[16];
    float rsum = 0.f;
    if (tid < 128)
        rsum = fminf(fminf(rm[tid], rm[128 + tid]),
                     fminf(rm[256 + tid], rm[384 + tid]));
#pragma unroll
    for (int o = 16; o; o >>= 1) {
        rsum += __shfl_xor_sync(0xffffffffu, rsum, o);
        sq   += __shfl_xor_sync(0xffffffffu, sq, o);
    }
    if (lane == 0) { ws[wid] = rsum; ws[8 + wid] = sq; }
    __syncthreads();
    if (tid == 0) {
        atomicAdd(&g_summin, (double)(ws[0] + ws[1] + ws[2] + ws[3]));
        double t = 0.0;
#pragma unroll
        for (int i = 0; i < 8; ++i) t += (double)ws[8 + i];
        atomicAdd(&g_sumx2, t);
        __threadfence();
        unsigned done = atomicAdd(&g_count, 1u);
        if (done == gridDim.x - 1) {                 // last CTA computes the loss
            double sx = atomicAdd(&g_sumx2, 0.0);
            double sm = atomicAdd(&g_summin, 0.0);
            double mean = (sx + sm) / (double)((long long)NVEC * EDIM);
            out[loss_idx] = (float)(1.25 * mean);    // (1 + BETA) * mean
        }
    }
}

extern "C" void kernel_launch(void* const* d_in, const int* in_sizes, int n_in,
                              void* d_out, int out_size) {
    (void)n_in; (void)in_sizes;
    const float* x  = (const float*)d_in[0];
    const float* cb = (const float*)d_in[1];
    float* out = (float*)d_out;

    cudaFuncSetAttribute(vq_mma_kernel, cudaFuncAttributeMaxDynamicSharedMemorySize,
                         SMEM_TOTAL);

    prep_kernel<<<256, 256>>>(cb);
    vq_mma_kernel<<<NVEC / CTA_M, 256, SMEM_TOTAL>>>(x, out, (long long)out_size - 1);
}